// round 10
// baseline (speedup 1.0000x reference)
#include <cuda_runtime.h>
#include <cuda_bf16.h>
#include <cuda_pipeline.h>
#include <mma.h>
#include <math.h>
#include <stdint.h>

using namespace nvcuda;

#define NTOT 4096
#define NSUP 1024
#define DIM  1024
#define MAXD 1024
#define TOPC 8
#define NITER 96
#define SBLK 32
#define SKW 24                                     // smem row stride (bf16), 48B

// ---------------- device scratch (allocation-free: __device__ globals) ------
__device__ float g_X [(size_t)NTOT * DIM];          // 16 MB fp32 inputs
__device__ __nv_bfloat16 g_Xh[(size_t)NTOT * DIM];  // 8 MB hi
__device__ __nv_bfloat16 g_Xl[(size_t)NTOT * DIM];  // 8 MB lo
__device__ float g_G [(size_t)NTOT * NTOT];         // 64 MB Gram matrix
__device__ float g_sq[NTOT];
__device__ int   g_top8[NTOT * TOPC];
__device__ __align__(16) int g_top4[NTOT * 4];
__device__ int   g_adj[(size_t)NTOT * MAXD];
__device__ int   g_deg[NTOT];
__device__ float g_Wv[(size_t)NTOT * MAXD];
__device__ float g_D[NTOT];
__device__ int2  g_edge[(size_t)NTOT * MAXD];
__device__ float g_y[NTOT * 2];
__device__ float g_xbuf[2][NTOT * 2];
__device__ unsigned g_count;
__device__ volatile unsigned g_gen;

// ---------------- stage 0: concat + bf16 hi/lo split ------------------------
__global__ void k_concat(const float* __restrict__ lab, const float* __restrict__ unlab) {
    size_t nl  = (size_t)NSUP * DIM;
    size_t tot = (size_t)NTOT * DIM;
    for (size_t idx = blockIdx.x * (size_t)blockDim.x + threadIdx.x; idx < tot;
         idx += gridDim.x * (size_t)blockDim.x) {
        float v = (idx < nl) ? lab[idx] : unlab[idx - nl];
        g_X[idx] = v;
        __nv_bfloat16 h = __float2bfloat16_rn(v);
        g_Xh[idx] = h;
        g_Xl[idx] = __float2bfloat16_rn(v - __bfloat162float(h));
    }
}

// ---------------- stage 1: row squared norms --------------------------------
__global__ void k_sq() {
    int i = blockIdx.x, tid = threadIdx.x;
    __shared__ float red[256];
    const float* r = g_X + (size_t)i * DIM;
    float s = 0.f;
    for (int k = tid; k < DIM; k += 256) { float v = r[k]; s += v * v; }
    red[tid] = s; __syncthreads();
    for (int st = 128; st > 0; st >>= 1) {
        if (tid < st) red[tid] += red[tid + st];
        __syncthreads();
    }
    if (tid == 0) g_sq[i] = red[0];
}

// ---------------- stage 2: split-bf16 tensor-core GEMM, cp.async pipeline ---
// G = Xh*Xh^T + Xh*Xl^T + Xl*Xh^T  (upper blocks, mirrored)
// smem: 2 stages x 4 tiles (Ah,Al,Bh,Bl) x 128 rows x 16 k (SKW=24 stride)
__global__ void __launch_bounds__(256) k_gemm() {
    int bi = blockIdx.y, bj = blockIdx.x;
    if (bj < bi) return;
    __shared__ __align__(16) __nv_bfloat16 S[2][4][128 * SKW];   // 48 KB

    int tid = threadIdx.x;
    int wid = tid >> 5;
    int rA = bi * 128, rB = bj * 128;
    int mbase = (wid >> 2) * 64, nbase = (wid & 3) * 32;

    wmma::fragment<wmma::accumulator, 16, 16, 16, float> acc[4][2];
    #pragma unroll
    for (int u = 0; u < 4; u++)
        #pragma unroll
        for (int v = 0; v < 2; v++) wmma::fill_fragment(acc[u][v], 0.0f);

    int lrow = tid >> 1;                       // 0..127
    int lhalf = (tid & 1) * 8;                 // 0 or 8 (bf16 elems, 16B chunk)
    size_t srcA = (size_t)(rA + lrow) * DIM + lhalf;
    size_t srcB = (size_t)(rB + lrow) * DIM + lhalf;
    unsigned dst = lrow * SKW + lhalf;

    const int NKT = DIM / 16;                  // 64 stages

    // prologue: stage 0
    __pipeline_memcpy_async(&S[0][0][dst], &g_Xh[srcA], 16);
    __pipeline_memcpy_async(&S[0][1][dst], &g_Xl[srcA], 16);
    __pipeline_memcpy_async(&S[0][2][dst], &g_Xh[srcB], 16);
    __pipeline_memcpy_async(&S[0][3][dst], &g_Xl[srcB], 16);
    __pipeline_commit();

    for (int kt = 0; kt < NKT; kt++) {
        if (kt + 1 < NKT) {
            int st = (kt + 1) & 1;
            size_t ko = (size_t)(kt + 1) * 16;
            __pipeline_memcpy_async(&S[st][0][dst], &g_Xh[srcA + ko], 16);
            __pipeline_memcpy_async(&S[st][1][dst], &g_Xl[srcA + ko], 16);
            __pipeline_memcpy_async(&S[st][2][dst], &g_Xh[srcB + ko], 16);
            __pipeline_memcpy_async(&S[st][3][dst], &g_Xl[srcB + ko], 16);
            __pipeline_commit();
            __pipeline_wait_prior(1);
        } else {
            __pipeline_wait_prior(0);
        }
        __syncthreads();

        int st = kt & 1;
        wmma::fragment<wmma::matrix_a, 16, 16, 16, __nv_bfloat16, wmma::row_major> ah[4], al[4];
        wmma::fragment<wmma::matrix_b, 16, 16, 16, __nv_bfloat16, wmma::col_major> bh[2], bl[2];
        #pragma unroll
        for (int u = 0; u < 4; u++) {
            wmma::load_matrix_sync(ah[u], &S[st][0][(mbase + u * 16) * SKW], SKW);
            wmma::load_matrix_sync(al[u], &S[st][1][(mbase + u * 16) * SKW], SKW);
        }
        #pragma unroll
        for (int v = 0; v < 2; v++) {
            wmma::load_matrix_sync(bh[v], &S[st][2][(nbase + v * 16) * SKW], SKW);
            wmma::load_matrix_sync(bl[v], &S[st][3][(nbase + v * 16) * SKW], SKW);
        }
        #pragma unroll
        for (int u = 0; u < 4; u++)
            #pragma unroll
            for (int v = 0; v < 2; v++) {
                wmma::mma_sync(acc[u][v], ah[u], bh[v], acc[u][v]);
                wmma::mma_sync(acc[u][v], ah[u], bl[v], acc[u][v]);
                wmma::mma_sync(acc[u][v], al[u], bh[v], acc[u][v]);
            }
        __syncthreads();                       // all reads done before next overwrite
    }

    #pragma unroll
    for (int u = 0; u < 4; u++)
        #pragma unroll
        for (int v = 0; v < 2; v++) {
            int gi = rA + mbase + u * 16;
            int gj = rB + nbase + v * 16;
            wmma::store_matrix_sync(&g_G[(size_t)gi * NTOT + gj], acc[u][v],
                                    NTOT, wmma::mem_row_major);
            if (bi != bj)
                wmma::store_matrix_sync(&g_G[(size_t)gj * NTOT + gi], acc[u][v],
                                        NTOT, wmma::mem_col_major);
        }
}

// ---------------- stage 3: top-8 smallest distances (warp-shuffle extract) --
__global__ void k_topk() {
    int i = blockIdx.x, tid = threadIdx.x;
    int lane = tid & 31, warp = tid >> 5;
    __shared__ float sv[8];
    __shared__ int   si[8];
    __shared__ float winv;
    __shared__ int   wini;

    float sqi = g_sq[i];
    const float4* Grow = (const float4*)(g_G + (size_t)i * NTOT);

    float bd[TOPC];
    int   bix[TOPC];
    #pragma unroll
    for (int q = 0; q < TOPC; q++) { bd[q] = INFINITY; bix[q] = 0x7fffffff; }

    for (int j4 = tid; j4 < NTOT / 4; j4 += 256) {
        float4 g = Grow[j4];
        float gv[4] = { g.x, g.y, g.z, g.w };
        #pragma unroll
        for (int e = 0; e < 4; e++) {
            int j = j4 * 4 + e;
            if (j == i) continue;
            float dv = sqi + g_sq[j] - 2.0f * gv[e];
            if (dv < bd[TOPC - 1] || (dv == bd[TOPC - 1] && j < bix[TOPC - 1])) {
                bd[TOPC - 1] = dv; bix[TOPC - 1] = j;
                #pragma unroll
                for (int q = TOPC - 1; q > 0; q--) {
                    if (bd[q] < bd[q - 1] || (bd[q] == bd[q - 1] && bix[q] < bix[q - 1])) {
                        float td = bd[q]; bd[q] = bd[q - 1]; bd[q - 1] = td;
                        int ti = bix[q]; bix[q] = bix[q - 1]; bix[q - 1] = ti;
                    } else break;
                }
            }
        }
    }

    int pos = 0;
    for (int round = 0; round < TOPC; round++) {
        float cand; int cidx;
        if (pos < TOPC) { cand = bd[pos]; cidx = bix[pos]; }
        else            { cand = INFINITY; cidx = 0x7fffffff; }
        float cv = cand; int ci2 = cidx;
        #pragma unroll
        for (int o = 16; o > 0; o >>= 1) {
            float ov = __shfl_down_sync(0xffffffffu, cv, o);
            int   oi = __shfl_down_sync(0xffffffffu, ci2, o);
            if (ov < cv || (ov == cv && oi < ci2)) { cv = ov; ci2 = oi; }
        }
        if (lane == 0) { sv[warp] = cv; si[warp] = ci2; }
        __syncthreads();
        if (tid == 0) {
            float best = sv[0]; int besti = si[0];
            #pragma unroll
            for (int w = 1; w < 8; w++) {
                if (sv[w] < best || (sv[w] == best && si[w] < besti)) {
                    best = sv[w]; besti = si[w];
                }
            }
            winv = best; wini = besti;
            g_top8[i * TOPC + round] = besti;
        }
        __syncthreads();
        if (pos < TOPC && bix[pos] == wini) pos++;
    }
}

// ---------------- stage 3b: fp64 refinement of top-8 -> exact top-4 ---------
__global__ void __launch_bounds__(256) k_refine() {
    int i = blockIdx.x;
    int c = threadIdx.x >> 5;
    int lane = threadIdx.x & 31;
    __shared__ double dd[TOPC];
    __shared__ int    cid[TOPC];

    int j = g_top8[i * TOPC + c];
    const float* xi = g_X + (size_t)i * DIM;
    const float* xj = g_X + (size_t)j * DIM;
    double s = 0.0;
    for (int k = lane; k < DIM; k += 32) {
        double d = (double)xi[k] - (double)xj[k];
        s += d * d;
    }
    #pragma unroll
    for (int o = 16; o > 0; o >>= 1) s += __shfl_down_sync(0xffffffffu, s, o);
    if (lane == 0) { dd[c] = s; cid[c] = j; }
    __syncthreads();
    if (threadIdx.x == 0) {
        bool used[TOPC];
        #pragma unroll
        for (int q = 0; q < TOPC; q++) used[q] = false;
        for (int r = 0; r < 4; r++) {
            int best = -1;
            for (int q = 0; q < TOPC; q++) {
                if (used[q]) continue;
                if (best < 0 || dd[q] < dd[best] ||
                    (dd[q] == dd[best] && cid[q] < cid[best])) best = q;
            }
            used[best] = true;
            g_top4[i * 4 + r] = cid[best];
        }
    }
}

// ---------------- stage 4: deterministic symmetric adjacency ----------------
__global__ void k_adj() {
    int i = blockIdx.x, tid = threadIdx.x;          // 128 threads
    __shared__ int myt[4];
    __shared__ int counts[128];
    __shared__ int offs[128];
    if (tid < 4) myt[tid] = g_top4[i * 4 + tid];
    __syncthreads();
    int t0 = myt[0], t1 = myt[1], t2 = myt[2], t3 = myt[3];

    int local[32]; int cnt = 0;
    int j0 = tid * 32;
    for (int q = 0; q < 32; q++) {
        int j = j0 + q;
        int4 tj = *(const int4*)&g_top4[j * 4];
        bool rev = (tj.x == i) | (tj.y == i) | (tj.z == i) | (tj.w == i);
        if (rev && j != t0 && j != t1 && j != t2 && j != t3) local[cnt++] = j;
    }
    counts[tid] = cnt;
    __syncthreads();
    if (tid == 0) {
        int s = 0;
        for (int k = 0; k < 128; k++) { offs[k] = s; s += counts[k]; }
        int dg = 4 + s;
        g_deg[i] = dg > MAXD ? MAXD : dg;
    }
    __syncthreads();
    int base = 4 + offs[tid];
    for (int q = 0; q < cnt; q++)
        if (base + q < MAXD) g_adj[(size_t)i * MAXD + base + q] = local[q];
    if (tid < 4) g_adj[(size_t)i * MAXD + tid] = myt[tid];
}

// ---------------- stage 5: edge weights + degrees + y -----------------------
__global__ void k_weights(const int* __restrict__ tgt) {
    int i = blockIdx.x * blockDim.x + threadIdx.x;
    if (i >= NTOT) return;
    int dg = g_deg[i];
    float sqi = g_sq[i];
    float s = 0.f;
    for (int l = 0; l < dg; l++) {
        int j = g_adj[(size_t)i * MAXD + l];
        float dist = (sqi + g_sq[j] - 2.0f * g_G[(size_t)i * NTOT + j]) * (1.0f / 1024.0f);
        float w = expf(-0.5f * dist);          // sigma = 1
        g_Wv[(size_t)i * MAXD + l] = w;
        s += w;
    }
    g_D[i] = s;
    float y0 = 0.f, y1 = 0.f;
    if (i < NSUP) {
        int t = tgt[i];
        y0 = (t == 0) ? 1.f : 0.f;
        y1 = (t == 1) ? 1.f : 0.f;
    }
    g_y[2 * i] = y0;
    g_y[2 * i + 1] = y1;
}

// ---------------- stage 6: packed edges, alpha * (d_i * W * d_j) ------------
__global__ void k_scale() {
    int i = blockIdx.x * blockDim.x + threadIdx.x;
    if (i >= NTOT) return;
    const float EPSF = 2.220446049250313e-16f;
    int dg = g_deg[i];
    float ri = sqrtf(1.0f / (g_D[i] + EPSF));
    for (int l = 0; l < dg; l++) {
        int j = g_adj[(size_t)i * MAXD + l];
        float rj = sqrtf(1.0f / (g_D[j] + EPSF));
        float sv = 0.99f * ((ri * g_Wv[(size_t)i * MAXD + l]) * rj);
        g_edge[(size_t)i * MAXD + l] = make_int2(j, __float_as_int(sv));
    }
}

// ---------------- grid barrier (sense-reversing, full publish) ---------------
__device__ __forceinline__ void gridbar() {
    __threadfence();
    __syncthreads();
    if (threadIdx.x == 0) {
        unsigned my = g_gen;
        if (atomicAdd(&g_count, 1) == SBLK - 1) {
            g_count = 0;
            __threadfence();
            g_gen = my + 1;
        } else {
            while (g_gen == my) { __nanosleep(64); }
        }
        __threadfence();
    }
    __syncthreads();
}

// ---------------- stage 8: Chebyshev solve, 32 CTAs, 8 lanes per row --------
__global__ void __launch_bounds__(1024, 1) k_solve(float* __restrict__ out) {
    unsigned gtid = blockIdx.x * 1024u + threadIdx.x;
    int row = gtid >> 3;
    int q8  = gtid & 7;

    const float theta = 1.0f, delta = 0.99f;
    const float sigma = theta / delta;
    float rho_prev = delta / theta;

    float b0 = g_y[2 * row], b1 = g_y[2 * row + 1];
    float d0 = b0, d1 = b1;
    float x0 = b0, x1 = b1;
    int dg = g_deg[row];
    const int2* ep = g_edge + (size_t)row * MAXD;

    if (q8 == 0)
        __stcg((float2*)&g_xbuf[0][2 * row], make_float2(x0, x1));
    gridbar();
    int p = 0;

    for (int it = 1; it < NITER; ++it) {
        float s0 = 0.f, s1 = 0.f;
        for (int l = q8; l < dg; l += 8) {
            int2 e = __ldg(&ep[l]);
            float w = __int_as_float(e.y);
            float2 xj = __ldcg((const float2*)&g_xbuf[p][2 * e.x]);
            s0 += w * xj.x;
            s1 += w * xj.y;
        }
        s0 += __shfl_down_sync(0xffffffffu, s0, 4, 8);
        s1 += __shfl_down_sync(0xffffffffu, s1, 4, 8);
        s0 += __shfl_down_sync(0xffffffffu, s0, 2, 8);
        s1 += __shfl_down_sync(0xffffffffu, s1, 2, 8);
        s0 += __shfl_down_sync(0xffffffffu, s0, 1, 8);
        s1 += __shfl_down_sync(0xffffffffu, s1, 1, 8);

        float rho = 1.0f / (2.0f * sigma - rho_prev);
        float c1 = rho * rho_prev, c2 = 2.0f * rho / delta;
        if (q8 == 0) {
            float rr0 = b0 - x0 + s0;
            float rr1 = b1 - x1 + s1;
            d0 = c1 * d0 + c2 * rr0;
            d1 = c1 * d1 + c2 * rr1;
            x0 += d0;
            x1 += d1;
            if (it != NITER - 1)
                __stcg((float2*)&g_xbuf[1 - p][2 * row], make_float2(x0, x1));
        }
        rho_prev = rho;
        if (it != NITER - 1) {
            gridbar();
            p ^= 1;
        }
    }

    if (q8 == 0 && row >= NSUP) {
        out[2 * (row - NSUP)]     = x0;
        out[2 * (row - NSUP) + 1] = x1;
    }
}

// ---------------- launch -----------------------------------------------------
extern "C" void kernel_launch(void* const* d_in, const int* in_sizes, int n_in,
                              void* d_out, int out_size) {
    const float* lab   = (const float*)d_in[0];
    const int*   tgt   = (const int*)d_in[1];
    const float* unlab = (const float*)d_in[2];
    float* out = (float*)d_out;

    k_concat<<<2048, 256>>>(lab, unlab);
    k_sq<<<NTOT, 256>>>();
    dim3 gg(32, 32);
    k_gemm<<<gg, 256>>>();
    k_topk<<<NTOT, 256>>>();
    k_refine<<<NTOT, 256>>>();
    k_adj<<<NTOT, 128>>>();
    k_weights<<<(NTOT + 255) / 256, 256>>>(tgt);
    k_scale<<<(NTOT + 255) / 256, 256>>>();
    k_solve<<<SBLK, 1024>>>(out);
}

// round 11
// speedup vs baseline: 1.3357x; 1.3357x over previous
#include <cuda_runtime.h>
#include <cuda_bf16.h>
#include <cuda_pipeline.h>
#include <mma.h>
#include <math.h>
#include <stdint.h>

using namespace nvcuda;

#define NTOT 4096
#define NSUP 1024
#define DIM  1024
#define MAXD 1024
#define TOPC 8
#define NITER 96
#define SBLK 32
#define SKW 24                                     // smem row stride (bf16), 48B

// ---------------- device scratch (allocation-free: __device__ globals) ------
__device__ float g_X [(size_t)NTOT * DIM];          // 16 MB fp32 inputs
__device__ __nv_bfloat16 g_Xh[(size_t)NTOT * DIM];  // 8 MB hi
__device__ __nv_bfloat16 g_Xl[(size_t)NTOT * DIM];  // 8 MB lo
__device__ float g_G [(size_t)NTOT * NTOT];         // 64 MB Gram matrix
__device__ float g_sq[NTOT];
__device__ int   g_top8[NTOT * TOPC];
__device__ __align__(16) int g_top4[NTOT * 4];
__device__ int   g_adj[(size_t)NTOT * MAXD];
__device__ int   g_deg[NTOT];
__device__ float g_Wv[(size_t)NTOT * MAXD];
__device__ float g_D[NTOT];
__device__ int2  g_edge[(size_t)NTOT * MAXD];
__device__ float g_y[NTOT * 2];
__device__ float g_xbuf[2][NTOT * 2];
__device__ unsigned g_count;
__device__ volatile unsigned g_gen;

// ---------------- stage 0: concat + bf16 hi/lo split ------------------------
__global__ void k_concat(const float* __restrict__ lab, const float* __restrict__ unlab) {
    size_t nl  = (size_t)NSUP * DIM;
    size_t tot = (size_t)NTOT * DIM;
    for (size_t idx = blockIdx.x * (size_t)blockDim.x + threadIdx.x; idx < tot;
         idx += gridDim.x * (size_t)blockDim.x) {
        float v = (idx < nl) ? lab[idx] : unlab[idx - nl];
        g_X[idx] = v;
        __nv_bfloat16 h = __float2bfloat16_rn(v);
        g_Xh[idx] = h;
        g_Xl[idx] = __float2bfloat16_rn(v - __bfloat162float(h));
    }
}

// ---------------- stage 1: row squared norms --------------------------------
__global__ void k_sq() {
    int i = blockIdx.x, tid = threadIdx.x;
    __shared__ float red[256];
    const float* r = g_X + (size_t)i * DIM;
    float s = 0.f;
    for (int k = tid; k < DIM; k += 256) { float v = r[k]; s += v * v; }
    red[tid] = s; __syncthreads();
    for (int st = 128; st > 0; st >>= 1) {
        if (tid < st) red[tid] += red[tid + st];
        __syncthreads();
    }
    if (tid == 0) g_sq[i] = red[0];
}

// ---------------- stage 2: split-bf16 wmma GEMM, single-sync pipeline -------
// G = Xh*Xh^T + Xh*Xl^T + Xl*Xh^T  (upper blocks, mirrored)
__global__ void __launch_bounds__(256) k_gemm() {
    int bi = blockIdx.y, bj = blockIdx.x;
    if (bj < bi) return;
    __shared__ __align__(16) __nv_bfloat16 S[2][4][128 * SKW];   // 48 KB exactly

    int tid = threadIdx.x;
    int wid = tid >> 5;
    int rA = bi * 128, rB = bj * 128;
    int mbase = (wid >> 2) * 64, nbase = (wid & 3) * 32;

    wmma::fragment<wmma::accumulator, 16, 16, 16, float> acc[4][2];
    #pragma unroll
    for (int u = 0; u < 4; u++)
        #pragma unroll
        for (int v = 0; v < 2; v++) wmma::fill_fragment(acc[u][v], 0.0f);

    int lrow = tid >> 1;                       // 0..127
    int lhalf = (tid & 1) * 8;                 // 0 or 8 (bf16 elems, 16B chunk)
    size_t srcA = (size_t)(rA + lrow) * DIM + lhalf;
    size_t srcB = (size_t)(rB + lrow) * DIM + lhalf;
    unsigned dst = lrow * SKW + lhalf;

    const int NKT = DIM / 16;                  // 64 stages

    // prologue: stage 0
    __pipeline_memcpy_async(&S[0][0][dst], &g_Xh[srcA], 16);
    __pipeline_memcpy_async(&S[0][1][dst], &g_Xl[srcA], 16);
    __pipeline_memcpy_async(&S[0][2][dst], &g_Xh[srcB], 16);
    __pipeline_memcpy_async(&S[0][3][dst], &g_Xl[srcB], 16);
    __pipeline_commit();

    for (int kt = 0; kt < NKT; kt++) {
        __pipeline_wait_prior(0);              // stage kt data resident
        __syncthreads();                       // also retires prior reads of buf (kt+1)&1
        if (kt + 1 < NKT) {                    // overlap next load with MMAs below
            int st = (kt + 1) & 1;
            size_t ko = (size_t)(kt + 1) * 16;
            __pipeline_memcpy_async(&S[st][0][dst], &g_Xh[srcA + ko], 16);
            __pipeline_memcpy_async(&S[st][1][dst], &g_Xl[srcA + ko], 16);
            __pipeline_memcpy_async(&S[st][2][dst], &g_Xh[srcB + ko], 16);
            __pipeline_memcpy_async(&S[st][3][dst], &g_Xl[srcB + ko], 16);
            __pipeline_commit();
        }

        int st = kt & 1;
        wmma::fragment<wmma::matrix_a, 16, 16, 16, __nv_bfloat16, wmma::row_major> ah[4], al[4];
        wmma::fragment<wmma::matrix_b, 16, 16, 16, __nv_bfloat16, wmma::col_major> bh[2], bl[2];
        #pragma unroll
        for (int u = 0; u < 4; u++) {
            wmma::load_matrix_sync(ah[u], &S[st][0][(mbase + u * 16) * SKW], SKW);
            wmma::load_matrix_sync(al[u], &S[st][1][(mbase + u * 16) * SKW], SKW);
        }
        #pragma unroll
        for (int v = 0; v < 2; v++) {
            wmma::load_matrix_sync(bh[v], &S[st][2][(nbase + v * 16) * SKW], SKW);
            wmma::load_matrix_sync(bl[v], &S[st][3][(nbase + v * 16) * SKW], SKW);
        }
        #pragma unroll
        for (int u = 0; u < 4; u++)
            #pragma unroll
            for (int v = 0; v < 2; v++) {
                wmma::mma_sync(acc[u][v], ah[u], bh[v], acc[u][v]);
                wmma::mma_sync(acc[u][v], ah[u], bl[v], acc[u][v]);
                wmma::mma_sync(acc[u][v], al[u], bh[v], acc[u][v]);
            }
    }

    #pragma unroll
    for (int u = 0; u < 4; u++)
        #pragma unroll
        for (int v = 0; v < 2; v++) {
            int gi = rA + mbase + u * 16;
            int gj = rB + nbase + v * 16;
            wmma::store_matrix_sync(&g_G[(size_t)gi * NTOT + gj], acc[u][v],
                                    NTOT, wmma::mem_row_major);
            if (bi != bj)
                wmma::store_matrix_sync(&g_G[(size_t)gj * NTOT + gi], acc[u][v],
                                        NTOT, wmma::mem_col_major);
        }
}

// ---------------- stage 3: top-8 smallest distances (static-index extract) --
__global__ void k_topk() {
    int i = blockIdx.x, tid = threadIdx.x;
    int lane = tid & 31, warp = tid >> 5;
    __shared__ float swv[64];
    __shared__ int   swi[64];

    float sqi = g_sq[i];
    const float4* Grow = (const float4*)(g_G + (size_t)i * NTOT);

    // prefetch all 4 chunks for MLP
    float4 gg[4];
    #pragma unroll
    for (int t = 0; t < 4; t++) gg[t] = Grow[tid + t * 256];

    float bd[TOPC];
    int   bix[TOPC];
    #pragma unroll
    for (int q = 0; q < TOPC; q++) { bd[q] = INFINITY; bix[q] = 0x7fffffff; }

    #pragma unroll
    for (int t = 0; t < 4; t++) {
        int j4 = tid + t * 256;
        float gv[4] = { gg[t].x, gg[t].y, gg[t].z, gg[t].w };
        #pragma unroll
        for (int e = 0; e < 4; e++) {
            int j = j4 * 4 + e;
            if (j == i) continue;
            float dv = sqi + g_sq[j] - 2.0f * gv[e];
            if (dv < bd[TOPC - 1] || (dv == bd[TOPC - 1] && j < bix[TOPC - 1])) {
                bd[TOPC - 1] = dv; bix[TOPC - 1] = j;
                #pragma unroll
                for (int q = TOPC - 1; q > 0; q--) {
                    if (bd[q] < bd[q - 1] || (bd[q] == bd[q - 1] && bix[q] < bix[q - 1])) {
                        float td = bd[q]; bd[q] = bd[q - 1]; bd[q - 1] = td;
                        int ti = bix[q]; bix[q] = bix[q - 1]; bix[q - 1] = ti;
                    } else break;
                }
            }
        }
    }

    // per-warp top-8 via used-bitmask rounds (all indexing static)
    unsigned used = 0;
    for (int r = 0; r < TOPC; r++) {
        float cv = INFINITY; int ci = 0x7fffffff; int cq = -1;
        #pragma unroll
        for (int q = 0; q < TOPC; q++) {
            if (!((used >> q) & 1u)) {
                if (bd[q] < cv || (bd[q] == cv && bix[q] < ci)) {
                    cv = bd[q]; ci = bix[q]; cq = q;
                }
            }
        }
        float mv = cv; int mi = ci;                // my candidate
        #pragma unroll
        for (int o = 16; o > 0; o >>= 1) {
            float ov = __shfl_xor_sync(0xffffffffu, cv, o);
            int   oi = __shfl_xor_sync(0xffffffffu, ci, o);
            if (ov < cv || (ov == cv && oi < ci)) { cv = ov; ci = oi; }
        }
        if (cq >= 0 && mi == ci && mv == cv) used |= (1u << cq);   // winner lane only (idx unique)
        if (lane == 0) { swv[warp * 8 + r] = cv; swi[warp * 8 + r] = ci; }
    }
    __syncthreads();

    // merge 8 sorted lists of 8 (thread 0; shared-mem dynamic indexing is cheap)
    if (tid == 0) {
        int head[8] = {0, 0, 0, 0, 0, 0, 0, 0};
        for (int r = 0; r < TOPC; r++) {
            float best = INFINITY; int besti = 0x7fffffff; int bw = -1;
            for (int w = 0; w < 8; w++) {
                int h = head[w];
                if (h < 8) {
                    float v = swv[w * 8 + h]; int ix = swi[w * 8 + h];
                    if (v < best || (v == best && ix < besti)) { best = v; besti = ix; bw = w; }
                }
            }
            head[bw]++;
            g_top8[i * TOPC + r] = besti;
        }
    }
}

// ---------------- stage 3b: fp64 refinement of top-8 -> exact top-4 ---------
__global__ void __launch_bounds__(256) k_refine() {
    int i = blockIdx.x;
    int c = threadIdx.x >> 5;
    int lane = threadIdx.x & 31;
    __shared__ double dd[TOPC];
    __shared__ int    cid[TOPC];

    int j = g_top8[i * TOPC + c];
    const float* xi = g_X + (size_t)i * DIM;
    const float* xj = g_X + (size_t)j * DIM;
    double s = 0.0;
    for (int k = lane; k < DIM; k += 32) {
        double d = (double)xi[k] - (double)xj[k];
        s += d * d;
    }
    #pragma unroll
    for (int o = 16; o > 0; o >>= 1) s += __shfl_down_sync(0xffffffffu, s, o);
    if (lane == 0) { dd[c] = s; cid[c] = j; }
    __syncthreads();
    if (threadIdx.x == 0) {
        bool used[TOPC];
        #pragma unroll
        for (int q = 0; q < TOPC; q++) used[q] = false;
        for (int r = 0; r < 4; r++) {
            int best = -1;
            for (int q = 0; q < TOPC; q++) {
                if (used[q]) continue;
                if (best < 0 || dd[q] < dd[best] ||
                    (dd[q] == dd[best] && cid[q] < cid[best])) best = q;
            }
            used[best] = true;
            g_top4[i * 4 + r] = cid[best];
        }
    }
}

// ---------------- stage 4: deterministic symmetric adjacency ----------------
__global__ void k_adj() {
    int i = blockIdx.x, tid = threadIdx.x;          // 128 threads
    __shared__ int myt[4];
    __shared__ int counts[128];
    __shared__ int offs[128];
    if (tid < 4) myt[tid] = g_top4[i * 4 + tid];
    __syncthreads();
    int t0 = myt[0], t1 = myt[1], t2 = myt[2], t3 = myt[3];

    int local[32]; int cnt = 0;
    int j0 = tid * 32;
    for (int q = 0; q < 32; q++) {
        int j = j0 + q;
        int4 tj = *(const int4*)&g_top4[j * 4];
        bool rev = (tj.x == i) | (tj.y == i) | (tj.z == i) | (tj.w == i);
        if (rev && j != t0 && j != t1 && j != t2 && j != t3) local[cnt++] = j;
    }
    counts[tid] = cnt;
    __syncthreads();
    if (tid == 0) {
        int s = 0;
        for (int k = 0; k < 128; k++) { offs[k] = s; s += counts[k]; }
        int dg = 4 + s;
        g_deg[i] = dg > MAXD ? MAXD : dg;
    }
    __syncthreads();
    int base = 4 + offs[tid];
    for (int q = 0; q < cnt; q++)
        if (base + q < MAXD) g_adj[(size_t)i * MAXD + base + q] = local[q];
    if (tid < 4) g_adj[(size_t)i * MAXD + tid] = myt[tid];
}

// ---------------- stage 5: edge weights + degrees + y -----------------------
__global__ void k_weights(const int* __restrict__ tgt) {
    int i = blockIdx.x * blockDim.x + threadIdx.x;
    if (i >= NTOT) return;
    int dg = g_deg[i];
    float sqi = g_sq[i];
    float s = 0.f;
    for (int l = 0; l < dg; l++) {
        int j = g_adj[(size_t)i * MAXD + l];
        float dist = (sqi + g_sq[j] - 2.0f * g_G[(size_t)i * NTOT + j]) * (1.0f / 1024.0f);
        float w = expf(-0.5f * dist);          // sigma = 1
        g_Wv[(size_t)i * MAXD + l] = w;
        s += w;
    }
    g_D[i] = s;
    float y0 = 0.f, y1 = 0.f;
    if (i < NSUP) {
        int t = tgt[i];
        y0 = (t == 0) ? 1.f : 0.f;
        y1 = (t == 1) ? 1.f : 0.f;
    }
    g_y[2 * i] = y0;
    g_y[2 * i + 1] = y1;
}

// ---------------- stage 6: packed edges, alpha * (d_i * W * d_j) ------------
__global__ void k_scale() {
    int i = blockIdx.x * blockDim.x + threadIdx.x;
    if (i >= NTOT) return;
    const float EPSF = 2.220446049250313e-16f;
    int dg = g_deg[i];
    float ri = sqrtf(1.0f / (g_D[i] + EPSF));
    for (int l = 0; l < dg; l++) {
        int j = g_adj[(size_t)i * MAXD + l];
        float rj = sqrtf(1.0f / (g_D[j] + EPSF));
        float sv = 0.99f * ((ri * g_Wv[(size_t)i * MAXD + l]) * rj);
        g_edge[(size_t)i * MAXD + l] = make_int2(j, __float_as_int(sv));
    }
}

// ---------------- grid barrier (writer-only fence) ---------------------------
__device__ __forceinline__ void gridbar(bool writer) {
    if (writer) __threadfence();                  // publish writer's stores
    __syncthreads();                              // order fences before arrive
    if (threadIdx.x == 0) {
        unsigned my = g_gen;
        if (atomicAdd(&g_count, 1) == SBLK - 1) {
            g_count = 0;
            __threadfence();
            g_gen = my + 1;
        } else {
            while (g_gen == my) { __nanosleep(32); }
        }
        __threadfence();
    }
    __syncthreads();
}

// ---------------- stage 8: Chebyshev solve, 32 CTAs, 8 lanes per row --------
__global__ void __launch_bounds__(1024, 1) k_solve(float* __restrict__ out) {
    unsigned gtid = blockIdx.x * 1024u + threadIdx.x;
    int row = gtid >> 3;
    int q8  = gtid & 7;
    bool writer = (q8 == 0);

    const float theta = 1.0f, delta = 0.99f;
    const float sigma = theta / delta;
    float rho_prev = delta / theta;

    float b0 = g_y[2 * row], b1 = g_y[2 * row + 1];
    float d0 = b0, d1 = b1;
    float x0 = b0, x1 = b1;
    int dg = g_deg[row];
    const int2* ep = g_edge + (size_t)row * MAXD;

    if (writer)
        __stcg((float2*)&g_xbuf[0][2 * row], make_float2(x0, x1));
    gridbar(writer);
    int p = 0;

    for (int it = 1; it < NITER; ++it) {
        float s0 = 0.f, s1 = 0.f;
        for (int l = q8; l < dg; l += 8) {
            int2 e = __ldg(&ep[l]);
            float w = __int_as_float(e.y);
            float2 xj = __ldcg((const float2*)&g_xbuf[p][2 * e.x]);
            s0 += w * xj.x;
            s1 += w * xj.y;
        }
        s0 += __shfl_down_sync(0xffffffffu, s0, 4, 8);
        s1 += __shfl_down_sync(0xffffffffu, s1, 4, 8);
        s0 += __shfl_down_sync(0xffffffffu, s0, 2, 8);
        s1 += __shfl_down_sync(0xffffffffu, s1, 2, 8);
        s0 += __shfl_down_sync(0xffffffffu, s0, 1, 8);
        s1 += __shfl_down_sync(0xffffffffu, s1, 1, 8);

        float rho = 1.0f / (2.0f * sigma - rho_prev);
        float c1 = rho * rho_prev, c2 = 2.0f * rho / delta;
        if (writer) {
            float rr0 = b0 - x0 + s0;
            float rr1 = b1 - x1 + s1;
            d0 = c1 * d0 + c2 * rr0;
            d1 = c1 * d1 + c2 * rr1;
            x0 += d0;
            x1 += d1;
            if (it != NITER - 1)
                __stcg((float2*)&g_xbuf[1 - p][2 * row], make_float2(x0, x1));
        }
        rho_prev = rho;
        if (it != NITER - 1) {
            gridbar(writer);
            p ^= 1;
        }
    }

    if (writer && row >= NSUP) {
        out[2 * (row - NSUP)]     = x0;
        out[2 * (row - NSUP) + 1] = x1;
    }
}

// ---------------- launch -----------------------------------------------------
extern "C" void kernel_launch(void* const* d_in, const int* in_sizes, int n_in,
                              void* d_out, int out_size) {
    const float* lab   = (const float*)d_in[0];
    const int*   tgt   = (const int*)d_in[1];
    const float* unlab = (const float*)d_in[2];
    float* out = (float*)d_out;

    k_concat<<<2048, 256>>>(lab, unlab);
    k_sq<<<NTOT, 256>>>();
    dim3 gg(32, 32);
    k_gemm<<<gg, 256>>>();
    k_topk<<<NTOT, 256>>>();
    k_refine<<<NTOT, 256>>>();
    k_adj<<<NTOT, 128>>>();
    k_weights<<<(NTOT + 255) / 256, 256>>>(tgt);
    k_scale<<<(NTOT + 255) / 256, 256>>>();
    k_solve<<<SBLK, 1024>>>(out);
}